// round 3
// baseline (speedup 1.0000x reference)
#include <cuda_runtime.h>

#define Bb 256
#define Tt 256
#define Ff 511
#define Uu 512
#define G4 2048   // 4*U

// ---------------- scratch (static device globals; no allocation) ----------------
__device__ float g_xcat[Bb*Tt*Uu];   // [B*T, U]  concat(inputs, score)      128MB
__device__ float g_Xx  [Bb*Tt*G4];   // [B*T, 4U] x @ enc_Wx + enc_b         512MB
__device__ float g_enc [Bb*Tt*Uu];   // [B, T, U] encoder outputs            134MB
__device__ float g_h [2][Bb*Uu];     // ping-pong hidden state
__device__ float g_c [2][Bb*Uu];     // ping-pong cell state
__device__ float g_xin[2][Bb*Uu];    // ping-pong decoder input

// ---------------- math helpers (accurate-fast) ----------------
__device__ __forceinline__ float sigf(float x){
    return __fdividef(1.f, 1.f + __expf(-x));
}
__device__ __forceinline__ float tanhf_fast(float x){
    float ax = fabsf(x);
    float t  = __expf(-2.f*ax);
    float r  = __fdividef(1.f - t, 1.f + t);
    return copysignf(r, x);
}

// ---------------- K0a: build xcat = concat(inputs, score) ----------------
__global__ void k_build(const float* __restrict__ inp, const float* __restrict__ score){
    int i  = blockIdx.x*256 + threadIdx.x;      // < B*T*U = 33.5M
    int u  = i & (Uu-1);
    int bt = i >> 9;                             // b*T + t
    g_xcat[i] = (u < Ff) ? inp[bt*Ff + u] : score[bt >> 8];
}

// ---------------- K0b: dec_in0 = mean_t(x), zero h0/c0 ----------------
__global__ void k_init(){
    int i = blockIdx.x*256 + threadIdx.x;        // < B*U
    int u = i & (Uu-1);
    int b = i >> 9;
    const float* p = &g_xcat[(b*Tt)*Uu + u];
    float s = 0.f;
    for (int t = 0; t < Tt; t++) s += p[t*Uu];
    g_xin[0][i] = s * (1.f/Tt);
    g_h[0][i] = 0.f;
    g_c[0][i] = 0.f;
}

// ---------------- K1: Xx = xcat @ enc_Wx + enc_b  (65536x512x2048) ----------------
__global__ void k_gemm_xx(const float* __restrict__ W, const float* __restrict__ bias){
    __shared__ float As[16][64];
    __shared__ float Bs[16][64];
    int tid = threadIdx.x;
    int tx = tid & 15, ty = tid >> 4;
    int row0 = blockIdx.y << 6, col0 = blockIdx.x << 6;
    float acc[4][4] = {};
    int ar = tid >> 2, ak = (tid & 3) << 2;
    int bk = tid >> 4, bc = (tid & 15) << 2;
    for (int k0 = 0; k0 < Uu; k0 += 16){
        float4 a = *(const float4*)&g_xcat[(row0+ar)*Uu + k0 + ak];
        As[ak  ][ar] = a.x; As[ak+1][ar] = a.y;
        As[ak+2][ar] = a.z; As[ak+3][ar] = a.w;
        *(float4*)&Bs[bk][bc] = *(const float4*)&W[(k0+bk)*G4 + col0 + bc];
        __syncthreads();
        #pragma unroll
        for (int kk = 0; kk < 16; kk++){
            float4 av = *(float4*)&As[kk][ty<<2];
            float4 bv = *(float4*)&Bs[kk][tx<<2];
            float aa[4] = {av.x, av.y, av.z, av.w};
            float bb[4] = {bv.x, bv.y, bv.z, bv.w};
            #pragma unroll
            for (int i = 0; i < 4; i++)
                #pragma unroll
                for (int j = 0; j < 4; j++) acc[i][j] += aa[i]*bb[j];
        }
        __syncthreads();
    }
    #pragma unroll
    for (int i = 0; i < 4; i++){
        int row = row0 + (ty<<2) + i;
        #pragma unroll
        for (int j = 0; j < 4; j++){
            int col = col0 + (tx<<2) + j;
            g_Xx[row*G4 + col] = acc[i][j] + bias[col];
        }
    }
}

// ---------------- K2: one encoder LSTM step (GEMM + gates fused) ----------------
// z = Xx[:,t,:] + h @ enc_Wh ; gates -> h,c ; h -> enc_out[:,t,:]
// Block: 32 rows x 32 gate-cols (per gate x4). 256 thr: ty=row(2), tx=col-pair.
__global__ void k_enc_step(const float* __restrict__ Wh, int t){
    const int par = t & 1;
    const float* __restrict__ h_in = g_h[par];
    const float* __restrict__ c_in = g_c[par];
    float* h_out = g_h[par^1];
    float* c_out = g_c[par^1];
    __shared__ float As[16][33];
    __shared__ float Bs[4][16][32];
    int tid = threadIdx.x;
    int tx = tid & 15, ty = tid >> 4;
    int col0 = blockIdx.x << 5;   // 16 tiles over 512
    int row0 = blockIdx.y << 5;   // 8 tiles over 256
    float acc[4][2][2] = {};
    int akk = tid & 15, ar = tid >> 4;
    int bc  = tid & 31, bkh = tid >> 5;
    for (int k0 = 0; k0 < Uu; k0 += 16){
        As[akk][ar]    = h_in[(row0+ar   )*Uu + k0 + akk];
        As[akk][ar+16] = h_in[(row0+ar+16)*Uu + k0 + akk];
        #pragma unroll
        for (int g = 0; g < 4; g++){
            Bs[g][bkh  ][bc] = Wh[(k0+bkh  )*G4 + g*Uu + col0 + bc];
            Bs[g][bkh+8][bc] = Wh[(k0+bkh+8)*G4 + g*Uu + col0 + bc];
        }
        __syncthreads();
        #pragma unroll
        for (int kk = 0; kk < 16; kk++){
            float a0 = As[kk][ty], a1 = As[kk][ty+16];
            #pragma unroll
            for (int g = 0; g < 4; g++){
                float2 b = *(float2*)&Bs[g][kk][tx<<1];
                acc[g][0][0] += a0*b.x; acc[g][0][1] += a0*b.y;
                acc[g][1][0] += a1*b.x; acc[g][1][1] += a1*b.y;
            }
        }
        __syncthreads();
    }
    #pragma unroll
    for (int rr = 0; rr < 2; rr++){
        int row = row0 + ty + (rr<<4);
        const float* zx = &g_Xx[(row*Tt + t)*G4];
        #pragma unroll
        for (int cc = 0; cc < 2; cc++){
            int col = col0 + (tx<<1) + cc;
            float zi = acc[0][rr][cc] + zx[col];
            float zf = acc[1][rr][cc] + zx[Uu   + col];
            float zg = acc[2][rr][cc] + zx[2*Uu + col];
            float zo = acc[3][rr][cc] + zx[3*Uu + col];
            float cn = sigf(zf)*c_in[row*Uu+col] + sigf(zi)*tanhf_fast(zg);
            float hn = sigf(zo)*tanhf_fast(cn);
            c_out[row*Uu+col] = cn;
            h_out[row*Uu+col] = hn;
            g_enc[(row*Tt + t)*Uu + col] = hn;
        }
    }
}

// ---------------- K3: one decoder LSTM step (K=1024 concat GEMM + gates) ----------------
__global__ void k_dec_step(const float* __restrict__ Wx, const float* __restrict__ Wh,
                           const float* __restrict__ bias, int s){
    const int par = s & 1;
    const float* __restrict__ xin  = g_xin[par];
    const float* __restrict__ h_in = g_h[par];
    const float* __restrict__ c_in = g_c[par];
    float* h_out = g_h[par^1];
    float* c_out = g_c[par^1];
    __shared__ float As[16][33];
    __shared__ float Bs[4][16][32];
    int tid = threadIdx.x;
    int tx = tid & 15, ty = tid >> 4;
    int col0 = blockIdx.x << 5;
    int row0 = blockIdx.y << 5;
    float acc[4][2][2] = {};
    int akk = tid & 15, ar = tid >> 4;
    int bc  = tid & 31, bkh = tid >> 5;
    for (int k0 = 0; k0 < 2*Uu; k0 += 16){
        const float* __restrict__ A = (k0 < Uu) ? xin : h_in;
        const float* __restrict__ W = (k0 < Uu) ? Wx  : Wh;
        int kb = (k0 < Uu) ? k0 : (k0 - Uu);
        As[akk][ar]    = A[(row0+ar   )*Uu + kb + akk];
        As[akk][ar+16] = A[(row0+ar+16)*Uu + kb + akk];
        #pragma unroll
        for (int g = 0; g < 4; g++){
            Bs[g][bkh  ][bc] = W[(kb+bkh  )*G4 + g*Uu + col0 + bc];
            Bs[g][bkh+8][bc] = W[(kb+bkh+8)*G4 + g*Uu + col0 + bc];
        }
        __syncthreads();
        #pragma unroll
        for (int kk = 0; kk < 16; kk++){
            float a0 = As[kk][ty], a1 = As[kk][ty+16];
            #pragma unroll
            for (int g = 0; g < 4; g++){
                float2 b = *(float2*)&Bs[g][kk][tx<<1];
                acc[g][0][0] += a0*b.x; acc[g][0][1] += a0*b.y;
                acc[g][1][0] += a1*b.x; acc[g][1][1] += a1*b.y;
            }
        }
        __syncthreads();
    }
    #pragma unroll
    for (int rr = 0; rr < 2; rr++){
        int row = row0 + ty + (rr<<4);
        #pragma unroll
        for (int cc = 0; cc < 2; cc++){
            int col = col0 + (tx<<1) + cc;
            float zi = acc[0][rr][cc] + bias[col];
            float zf = acc[1][rr][cc] + bias[Uu   + col];
            float zg = acc[2][rr][cc] + bias[2*Uu + col];
            float zo = acc[3][rr][cc] + bias[3*Uu + col];
            float cn = sigf(zf)*c_in[row*Uu+col] + sigf(zi)*tanhf_fast(zg);
            float hn = sigf(zo)*tanhf_fast(cn);
            c_out[row*Uu+col] = cn;
            h_out[row*Uu+col] = hn;
        }
    }
}

// ---------------- K4: attention for one decoder step (one block per batch b) ----------------
// scores = h . enc[b,:,:], softmax(scores*w+b) -> out[b,s,:], xin = ptr @ enc[b,:,:]
__global__ void k_attn(const float* __restrict__ pw, const float* __restrict__ pb,
                       float* __restrict__ out, int s){
    int b = blockIdx.x;
    int p = (s & 1) ^ 1;                       // buffer holding h from this step
    __shared__ float hs[Uu];
    __shared__ float pr[Tt];
    __shared__ float red[8];
    int tid = threadIdx.x;
    hs[tid]       = g_h[p][b*Uu + tid];
    hs[tid + 256] = g_h[p][b*Uu + tid + 256];
    __syncthreads();
    int w = tid >> 5, lane = tid & 31;
    const float* encb = &g_enc[b*Tt*Uu];
    // phase 1: dot products, warp-per-t
    for (int t = w; t < Tt; t += 8){
        const float* e = &encb[t*Uu];
        float sum = 0.f;
        #pragma unroll
        for (int u = lane*4; u < Uu; u += 128){
            float4 ev = *(const float4*)&e[u];
            float4 hv = *(const float4*)&hs[u];
            sum += ev.x*hv.x + ev.y*hv.y + ev.z*hv.z + ev.w*hv.w;
        }
        #pragma unroll
        for (int off = 16; off; off >>= 1) sum += __shfl_xor_sync(0xffffffffu, sum, off);
        if (lane == 0) pr[t] = sum;
    }
    __syncthreads();
    // phase 2: softmax over T (one element per thread)
    float wv = *pw, bv = *pb;
    float logit = pr[tid]*wv + bv;
    float m = logit;
    #pragma unroll
    for (int off = 16; off; off >>= 1) m = fmaxf(m, __shfl_xor_sync(0xffffffffu, m, off));
    if (lane == 0) red[w] = m;
    __syncthreads();
    m = red[0];
    #pragma unroll
    for (int i = 1; i < 8; i++) m = fmaxf(m, red[i]);
    float e  = __expf(logit - m);
    float sm = e;
    #pragma unroll
    for (int off = 16; off; off >>= 1) sm += __shfl_xor_sync(0xffffffffu, sm, off);
    __syncthreads();                 // everyone done reading red (max)
    if (lane == 0) red[w] = sm;
    __syncthreads();
    sm = 0.f;
    #pragma unroll
    for (int i = 0; i < 8; i++) sm += red[i];
    float pv = e * __fdividef(1.f, sm);
    pr[tid] = pv;
    out[(b*Tt + s)*Tt + tid] = pv;
    __syncthreads();
    // phase 3: context xin[b,u] = sum_t pr[t] * enc[b,t,u]
    int u0 = tid << 1;
    float x0 = 0.f, x1 = 0.f;
    for (int t = 0; t < Tt; t++){
        float pt = pr[t];
        float2 ev = *(const float2*)&encb[t*Uu + u0];
        x0 += pt*ev.x; x1 += pt*ev.y;
    }
    g_xin[p][b*Uu + u0    ] = x0;
    g_xin[p][b*Uu + u0 + 1] = x1;
}

// ---------------- launch ----------------
extern "C" void kernel_launch(void* const* d_in, const int* in_sizes, int n_in,
                              void* d_out, int out_size){
    const float* inputs = (const float*)d_in[0];
    const float* score  = (const float*)d_in[1];
    const float* eWx    = (const float*)d_in[2];
    const float* eWh    = (const float*)d_in[3];
    const float* eb     = (const float*)d_in[4];
    const float* dWx    = (const float*)d_in[5];
    const float* dWh    = (const float*)d_in[6];
    const float* db     = (const float*)d_in[7];
    const float* pw     = (const float*)d_in[8];
    const float* pb     = (const float*)d_in[9];
    float* out = (float*)d_out;

    k_build<<<Bb*Tt*Uu/256, 256>>>(inputs, score);
    k_init<<<Bb*Uu/256, 256>>>();
    k_gemm_xx<<<dim3(G4/64, Bb*Tt/64), 256>>>(eWx, eb);

    for (int t = 0; t < Tt; t++)
        k_enc_step<<<dim3(16, 8), 256>>>(eWh, t);

    for (int s = 0; s < Tt; s++){
        k_dec_step<<<dim3(16, 8), 256>>>(dWx, dWh, db, s);
        k_attn<<<Bb, 256>>>(pw, pb, out, s);
    }
}

// round 10
// speedup vs baseline: 2.3351x; 2.3351x over previous
#include <cuda_runtime.h>
#include <cuda_fp16.h>
#include <cstdint>

#define Bb 256
#define Tt 256
#define Ff 511
#define Uu 512
#define G4 2048   // 4*U

// ---------------- scratch (static device globals; no allocation) ----------------
__device__ float g_xcat[Bb*Tt*Uu];                     // [B*T, U] concat(inputs, score)
__device__ float g_Xx  [Bb*Tt*G4];                     // [B*T, 4U] x @ enc_Wx (unit-interleaved cols)
__device__ __half g_ench[(size_t)Bb*Tt*Uu];            // [B, T, U] encoder outputs (fp16, L2-resident)
__device__ float g_h [2][Bb*Uu];                       // encoder hidden ping-pong
__device__ float g_c [2][Bb*Uu];                       // encoder cell ping-pong
__device__ float g_xh[2][Bb*2*Uu];                     // decoder [xin | h] concat ping-pong
__device__ float g_cd[2][Bb*Uu];                       // decoder cell ping-pong
// tf32 fragment weights, hi/lo split: [kb][nb][lane][4] = {b0_hi, b1_hi, b0_lo, b1_lo}
// column-permuted: n' = u*4 + gate
__device__ __align__(16) uint32_t g_Wxf[(size_t)64 *256*32*4];   // K=512  (8MB)
__device__ __align__(16) uint32_t g_Whf[(size_t)64 *256*32*4];   // K=512  (8MB)
__device__ __align__(16) uint32_t g_Wdf[(size_t)128*256*32*4];   // K=1024 (16MB)

// ---------------- math helpers ----------------
__device__ __forceinline__ float sigf(float x){
    return __fdividef(1.f, 1.f + __expf(-x));
}
__device__ __forceinline__ float tanhf_fast(float x){
    float ax = fabsf(x);
    float t  = __expf(-2.f*ax);
    float r  = __fdividef(1.f - t, 1.f + t);
    return copysignf(r, x);
}
__device__ __forceinline__ uint32_t f2tf(float f){
    uint32_t u; asm("cvt.rna.tf32.f32 %0, %1;" : "=r"(u) : "f"(f)); return u;
}
__device__ __forceinline__ void mma_tf32(float* c, const uint32_t* a, const uint32_t* b){
    asm volatile(
        "mma.sync.aligned.m16n8k8.row.col.f32.tf32.tf32.f32 "
        "{%0,%1,%2,%3}, {%4,%5,%6,%7}, {%8,%9}, {%0,%1,%2,%3};"
        : "+f"(c[0]), "+f"(c[1]), "+f"(c[2]), "+f"(c[3])
        : "r"(a[0]), "r"(a[1]), "r"(a[2]), "r"(a[3]), "r"(b[0]), "r"(b[1]));
}

// ---------------- K0a: build xcat = concat(inputs, score) ----------------
__global__ void k_build(const float* __restrict__ inp, const float* __restrict__ score){
    int i  = blockIdx.x*256 + threadIdx.x;
    int u  = i & (Uu-1);
    int bt = i >> 9;
    g_xcat[i] = (u < Ff) ? inp[bt*Ff + u] : score[bt >> 8];
}

// ---------------- K0b: dec_in0 = mean_t(x); zero enc state ----------------
__global__ void k_init(){
    int i = blockIdx.x*256 + threadIdx.x;        // < B*U
    int u = i & (Uu-1);
    int b = i >> 9;
    const float* p = &g_xcat[(b*Tt)*Uu + u];
    float s = 0.f;
    for (int t = 0; t < Tt; t++) s += p[t*Uu];
    g_xh[0][b*2*Uu + u] = s * (1.f/Tt);
    g_h[0][i] = 0.f;
    g_c[0][i] = 0.f;
}

// ---------------- weight rearrange: hi/lo tf32 fragments, unit-interleaved cols ----------------
// fragment col n' = nb*8+gg maps to original col c = (n'&3)*512 + (n'>>2)
__global__ void k_rearr(const float* __restrict__ W, int dst_sel, int kb_off, int Krows){
    uint32_t* Wf = (dst_sel == 0) ? g_Wxf : (dst_sel == 1) ? g_Whf : g_Wdf;
    int idx = blockIdx.x*256 + threadIdx.x;      // 64*256*32 threads
    int lane = idx & 31;
    int nb   = (idx >> 5) & 255;
    int kb   = idx >> 13;
    if (kb >= Krows/8) return;
    int gg = lane >> 2, tig = lane & 3;
    int np = nb*8 + gg;                 // permuted col
    int c  = (np & 3)*Uu + (np >> 2);   // original col = gate*512 + u
    float v0 = W[(kb*8 + tig    )*G4 + c];
    float v1 = W[(kb*8 + tig + 4)*G4 + c];
    uint32_t h0 = f2tf(v0), h1 = f2tf(v1);
    uint32_t l0 = f2tf(v0 - __uint_as_float(h0));
    uint32_t l1 = f2tf(v1 - __uint_as_float(h1));
    uint4 v; v.x = h0; v.y = h1; v.z = l0; v.w = l1;
    *(uint4*)&Wf[(((size_t)(kb + kb_off)*256 + nb)*32 + lane)*4] = v;
}

// ---------------- 3xTF32 MMA mainloop: acc = A[32-row tile] @ B[128-col tile] ----------------
// pool carve-out: As = pool[0..2047], Bs = pool[2048..10239]  (40KB)
__device__ __forceinline__ void mma_main(const float* __restrict__ A, int lda,
                                         const uint32_t* __restrict__ Bf, int K,
                                         uint32_t* pool, float (&acc)[4][4]){
    uint32_t* As = pool;          // [buf(2)][row(4)][lane(32)][slot(8)]
    uint32_t* Bs = pool + 2048;   // [buf(2)][row(32)][lane(32)][slot(4)]

    const int t    = threadIdx.x;
    const int lane = t & 31;
    const int wid  = t >> 5;
    const int warpM = wid & 1;
    const int warpN = wid >> 1;

    const int row0 = blockIdx.y << 5;
    const int col0 = blockIdx.x << 7;
    const int NK   = K >> 4;

    const int ar = t >> 3;               // 0..31
    const int ac = (t & 7) << 1;         // 0,2,..,14
    const float* Aptr = &A[(size_t)(row0 + ar)*lda + ac];
    int s_idx[2];
    #pragma unroll
    for (int j = 0; j < 2; j++){
        int c = ac + j;
        int srow  = ((c >> 3) << 1) + (ar >> 4);
        int slane = ((ar & 7) << 2) + (c & 3);
        int sslot = (((c >> 2) & 1) << 1) + ((ar >> 3) & 1);
        s_idx[j] = (srow*32 + slane)*8 + sslot;
    }
    const uint32_t* Bbase = Bf + (size_t)(col0 >> 3)*128;

    #pragma unroll
    for (int i = 0; i < 4; i++)
        #pragma unroll
        for (int j = 0; j < 4; j++) acc[i][j] = 0.f;

    // ---- stage chunk 0 ----
    float2 Av = *(const float2*)Aptr;
    uint4  Bv[4];
    #pragma unroll
    for (int kb = 0; kb < 2; kb++){
        const uint32_t* src = Bbase + (size_t)kb*32768;
        Bv[kb*2  ] = *(const uint4*)(src + t*4);
        Bv[kb*2+1] = *(const uint4*)(src + 1024 + t*4);
    }
    {
        float av[2] = {Av.x, Av.y};
        #pragma unroll
        for (int j = 0; j < 2; j++){
            uint32_t hi = f2tf(av[j]);
            As[s_idx[j]    ] = hi;
            As[s_idx[j] + 4] = f2tf(av[j] - __uint_as_float(hi));
        }
        #pragma unroll
        for (int kb = 0; kb < 2; kb++){
            *(uint4*)(Bs + kb*2048 + t*4)        = Bv[kb*2];
            *(uint4*)(Bs + kb*2048 + 1024 + t*4) = Bv[kb*2+1];
        }
    }
    __syncthreads();

    int cur = 0;
    for (int kc = 0; kc < NK; kc++){
        if (kc + 1 < NK){
            Av = *(const float2*)(Aptr + (kc+1)*16);
            #pragma unroll
            for (int kb = 0; kb < 2; kb++){
                const uint32_t* src = Bbase + (size_t)((kc+1)*2 + kb)*32768;
                Bv[kb*2  ] = *(const uint4*)(src + t*4);
                Bv[kb*2+1] = *(const uint4*)(src + 1024 + t*4);
            }
        }
        #pragma unroll
        for (int ks = 0; ks < 2; ks++){
            uint32_t ah[4], al[4];
            const uint32_t* abase = As + cur*1024 + ((ks*2 + warpM)*32 + lane)*8;
            *(uint4*)ah = *(const uint4*)(abase);
            *(uint4*)al = *(const uint4*)(abase + 4);
            #pragma unroll
            for (int nbl = 0; nbl < 4; nbl++){
                uint4 bv = *(const uint4*)(Bs + cur*4096 + ((ks*16 + warpN*4 + nbl)*32 + lane)*4);
                uint32_t bh[2]  = {bv.x, bv.y};
                uint32_t blo[2] = {bv.z, bv.w};
                mma_tf32(acc[nbl], ah, blo);
                mma_tf32(acc[nbl], al, bh);
                mma_tf32(acc[nbl], ah, bh);
            }
        }
        if (kc + 1 < NK){
            float av[2] = {Av.x, Av.y};
            int nb2 = (cur^1)*1024;
            #pragma unroll
            for (int j = 0; j < 2; j++){
                uint32_t hi = f2tf(av[j]);
                As[nb2 + s_idx[j]    ] = hi;
                As[nb2 + s_idx[j] + 4] = f2tf(av[j] - __uint_as_float(hi));
            }
            uint32_t* bl = Bs + (cur^1)*4096;
            #pragma unroll
            for (int kb = 0; kb < 2; kb++){
                *(uint4*)(bl + kb*2048 + t*4)        = Bv[kb*2];
                *(uint4*)(bl + kb*2048 + 1024 + t*4) = Bv[kb*2+1];
            }
        }
        __syncthreads();
        cur ^= 1;
    }
    // after the final __syncthreads(), all warps are done reading pool -> reusable
}

// ---------------- big input projection: plain store (interleaved cols) ----------------
__global__ void k_gemm_xx_g(){
    __shared__ __align__(16) uint32_t pool[10240];
    float acc[4][4];
    mma_main(g_xcat, Uu, g_Wxf, Uu, pool, acc);
    const int lane = threadIdx.x & 31, wid = threadIdx.x >> 5;
    const int warpM = wid & 1, warpN = wid >> 1;
    const int gg = lane >> 2, tig = lane & 3;
    const int r0 = (blockIdx.y << 5) + warpM*16 + gg;
    const int col0 = blockIdx.x << 7;
    #pragma unroll
    for (int nbl = 0; nbl < 4; nbl++){
        int col = col0 + (warpN*4 + nbl)*8 + 2*tig;
        *(float2*)&g_Xx[(size_t)r0*G4 + col]     = make_float2(acc[nbl][0], acc[nbl][1]);
        *(float2*)&g_Xx[(size_t)(r0+8)*G4 + col] = make_float2(acc[nbl][2], acc[nbl][3]);
    }
}

// ---------------- fused encoder step: GEMM + Xx + bias + gates + state ----------------
__global__ void k_enc_step(const float* __restrict__ eb, int t){
    __shared__ __align__(16) uint32_t pool[10240];
    float acc[4][4];
    const int par = t & 1;
    mma_main(g_h[par], Uu, g_Whf, Uu, pool, acc);

    float* zs = reinterpret_cast<float*>(pool);     // [32][132] z tile (reuses pool)
    const int lane = threadIdx.x & 31, wid = threadIdx.x >> 5;
    const int warpM = wid & 1, warpN = wid >> 1;
    const int gg = lane >> 2, tig = lane & 3;
    const int rl = warpM*16 + gg;
    #pragma unroll
    for (int nbl = 0; nbl < 4; nbl++){
        int c = (warpN*4 + nbl)*8 + 2*tig;
        zs[rl*132 + c]     = acc[nbl][0]; zs[rl*132 + c + 1]     = acc[nbl][1];
        zs[(rl+8)*132 + c] = acc[nbl][2]; zs[(rl+8)*132 + c + 1] = acc[nbl][3];
    }
    __syncthreads();

    const int th  = threadIdx.x;
    const int row = th >> 3;
    const int u4  = th & 7;
    const int b   = (blockIdx.y << 5) + row;
    const int col0 = blockIdx.x << 7;
    #pragma unroll
    for (int i = 0; i < 4; i++){
        int ul = u4*4 + i;
        int ug = (blockIdx.x << 5) + ul;
        float4 z4 = *(float4*)&zs[row*132 + ul*4];
        float4 xx = *(const float4*)&g_Xx[((size_t)b*Tt + t)*G4 + col0 + ul*4];
        float zi = z4.x + xx.x + eb[ug];
        float zf = z4.y + xx.y + eb[Uu   + ug];
        float zg = z4.z + xx.z + eb[2*Uu + ug];
        float zo = z4.w + xx.w + eb[3*Uu + ug];
        int idx = b*Uu + ug;
        float cn = sigf(zf)*g_c[par][idx] + sigf(zi)*tanhf_fast(zg);
        float hn = sigf(zo)*tanhf_fast(cn);
        g_c[par^1][idx] = cn;
        g_h[par^1][idx] = hn;
        g_ench[((size_t)b*Tt + t)*Uu + ug] = __float2half(hn);
    }
}

// ---------------- dec init: copy enc-final h,c into decoder state ----------------
__global__ void k_init_dec(){
    int i = blockIdx.x*256 + threadIdx.x;
    int u = i & (Uu-1);
    int b = i >> 9;
    g_xh[0][b*2*Uu + Uu + u] = g_h[0][i];
    g_cd[0][i] = g_c[0][i];
}

// ---------------- fused decoder step: GEMM (K=1024) + bias + gates + state ----------------
__global__ void k_dec_step(const float* __restrict__ db, int s){
    __shared__ __align__(16) uint32_t pool[10240];
    float acc[4][4];
    const int par = s & 1;
    mma_main(g_xh[par], 2*Uu, g_Wdf, 2*Uu, pool, acc);

    float* zs = reinterpret_cast<float*>(pool);
    const int lane = threadIdx.x & 31, wid = threadIdx.x >> 5;
    const int warpM = wid & 1, warpN = wid >> 1;
    const int gg = lane >> 2, tig = lane & 3;
    const int rl = warpM*16 + gg;
    #pragma unroll
    for (int nbl = 0; nbl < 4; nbl++){
        int c = (warpN*4 + nbl)*8 + 2*tig;
        zs[rl*132 + c]     = acc[nbl][0]; zs[rl*132 + c + 1]     = acc[nbl][1];
        zs[(rl+8)*132 + c] = acc[nbl][2]; zs[(rl+8)*132 + c + 1] = acc[nbl][3];
    }
    __syncthreads();

    const int th  = threadIdx.x;
    const int row = th >> 3;
    const int u4  = th & 7;
    const int b   = (blockIdx.y << 5) + row;
    #pragma unroll
    for (int i = 0; i < 4; i++){
        int ul = u4*4 + i;
        int ug = (blockIdx.x << 5) + ul;
        float4 z4 = *(float4*)&zs[row*132 + ul*4];
        float zi = z4.x + db[ug];
        float zf = z4.y + db[Uu   + ug];
        float zg = z4.z + db[2*Uu + ug];
        float zo = z4.w + db[3*Uu + ug];
        int idx = b*Uu + ug;
        float cn = sigf(zf)*g_cd[par][idx] + sigf(zi)*tanhf_fast(zg);
        float hn = sigf(zo)*tanhf_fast(cn);
        g_cd[par^1][idx] = cn;
        g_xh[par^1][b*2*Uu + Uu + ug] = hn;
    }
}

// ---------------- attention (one block per batch row; enc in fp16) ----------------
__global__ void k_attn(const float* __restrict__ pw, const float* __restrict__ pb,
                       float* __restrict__ out, int s){
    int b = blockIdx.x;
    int p = (s & 1) ^ 1;                 // buffer holding this step's h / receiving xin
    __shared__ float hs[Uu];
    __shared__ float pr[Tt];
    __shared__ float red[8];
    int tid = threadIdx.x;
    hs[tid]       = g_xh[p][b*2*Uu + Uu + tid];
    hs[tid + 256] = g_xh[p][b*2*Uu + Uu + tid + 256];
    __syncthreads();
    int w = tid >> 5, lane = tid & 31;
    const __half* encb = &g_ench[(size_t)b*Tt*Uu];
    for (int t = w; t < Tt; t += 8){
        const __half2* e2 = reinterpret_cast<const __half2*>(encb + t*Uu);
        float sum = 0.f;
        #pragma unroll
        for (int u = lane*8; u < Uu; u += 256){
            int h2 = u >> 1;
            float2 p0 = __half22float2(e2[h2  ]);
            float2 p1 = __half22float2(e2[h2+1]);
            float2 p2 = __half22float2(e2[h2+2]);
            float2 p3 = __half22float2(e2[h2+3]);
            sum += p0.x*hs[u  ] + p0.y*hs[u+1] + p1.x*hs[u+2] + p1.y*hs[u+3]
                 + p2.x*hs[u+4] + p2.y*hs[u+5] + p3.x*hs[u+6] + p3.y*hs[u+7];
        }
        #pragma unroll
        for (int off = 16; off; off >>= 1) sum += __shfl_xor_sync(0xffffffffu, sum, off);
        if (lane == 0) pr[t] = sum;
    }
    __syncthreads();
    float wv = *pw, bv = *pb;
    float logit = pr[tid]*wv + bv;
    float m = logit;
    #pragma unroll
    for (int off = 16; off; off >>= 1) m = fmaxf(m, __shfl_xor_sync(0xffffffffu, m, off));
    if (lane == 0) red[w] = m;
    __syncthreads();
    m = red[0];
    #pragma unroll
    for (int i = 1; i < 8; i++) m = fmaxf(m, red[i]);
    float e  = __expf(logit - m);
    float sm = e;
    #pragma unroll
    for (int off = 16; off; off >>= 1) sm += __shfl_xor_sync(0xffffffffu, sm, off);
    __syncthreads();
    if (lane == 0) red[w] = sm;
    __syncthreads();
    sm = 0.f;
    #pragma unroll
    for (int i = 0; i < 8; i++) sm += red[i];
    float pv = e * __fdividef(1.f, sm);
    pr[tid] = pv;
    out[((size_t)b*Tt + s)*Tt + tid] = pv;
    __syncthreads();
    const __half2* ep = reinterpret_cast<const __half2*>(encb);
    float x0 = 0.f, x1 = 0.f;
    for (int t = 0; t < Tt; t++){
        float pt = pr[t];
        float2 ev = __half22float2(ep[t*(Uu/2) + tid]);
        x0 += pt*ev.x; x1 += pt*ev.y;
    }
    g_xh[p][b*2*Uu + tid*2    ] = x0;
    g_xh[p][b*2*Uu + tid*2 + 1] = x1;
}

// ---------------- launch ----------------
extern "C" void kernel_launch(void* const* d_in, const int* in_sizes, int n_in,
                              void* d_out, int out_size){
    const float* inputs = (const float*)d_in[0];
    const float* score  = (const float*)d_in[1];
    const float* eWx    = (const float*)d_in[2];
    const float* eWh    = (const float*)d_in[3];
    const float* eb     = (const float*)d_in[4];
    const float* dWx    = (const float*)d_in[5];
    const float* dWh    = (const float*)d_in[6];
    const float* db     = (const float*)d_in[7];
    const float* pw     = (const float*)d_in[8];
    const float* pb     = (const float*)d_in[9];
    float* out = (float*)d_out;

    k_build<<<Bb*Tt*Uu/256, 256>>>(inputs, score);
    k_init<<<Bb*Uu/256, 256>>>();

    // weight rearrange (hi/lo tf32 fragments, unit-interleaved columns)
    k_rearr<<<2048, 256>>>(eWx, 0, 0,  512);
    k_rearr<<<2048, 256>>>(eWh, 1, 0,  512);
    k_rearr<<<2048, 256>>>(dWx, 2, 0,  512);
    k_rearr<<<2048, 256>>>(dWh, 2, 64, 512);

    // big input projection: [65536 x 512] @ [512 x 2048]
    k_gemm_xx_g<<<dim3(16, 2048), 256>>>();

    // encoder recurrence (1 fused kernel per step)
    for (int t = 0; t < Tt; t++)
        k_enc_step<<<dim3(16, 8), 256>>>(eb, t);

    k_init_dec<<<Bb*Uu/256, 256>>>();

    // decoder recurrence + attention (2 kernels per step)
    for (int s = 0; s < Tt; s++){
        k_dec_step<<<dim3(16, 8), 256>>>(db, s);
        k_attn<<<Bb, 256>>>(pw, pb, out, s);
    }
}

// round 12
// speedup vs baseline: 3.3284x; 1.4254x over previous
#include <cuda_runtime.h>
#include <cuda_fp16.h>
#include <cuda_bf16.h>
#include <cstdint>

#define Bb 256
#define Tt 256
#define Ff 511
#define Uu 512
#define G4 2048   // 4*U

// ---------------- scratch (static device globals; no allocation) ----------------
__device__ float g_xcat[Bb*Tt*Uu];                     // [B*T, U] concat(inputs, score)
__device__ float g_Xx  [Bb*Tt*G4];                     // [B*T, 4U] x @ enc_Wx (unit-interleaved cols)
__device__ __half g_ench[(size_t)Bb*Tt*Uu];            // [B, T, U] encoder outputs (fp16, L2-resident)
__device__ float g_h [2][Bb*Uu];                       // encoder hidden ping-pong
__device__ float g_c [2][Bb*Uu];                       // encoder cell ping-pong
__device__ float g_xh[2][Bb*2*Uu];                     // decoder [xin | h] concat ping-pong
__device__ float g_cd[2][Bb*Uu];                       // decoder cell ping-pong
// bf16-split fragment weights: [kb16][nb][lane][4 uints] = {b0_hi, b1_hi, b0_lo, b1_lo}
// (each uint = 2 bf16, k-pair packed; column-permuted n' = u*4 + gate)
__device__ __align__(16) uint32_t g_Wxf[(size_t)32*256*128];   // K=512  (4MB)
__device__ __align__(16) uint32_t g_Whf[(size_t)32*256*128];   // K=512  (4MB)
__device__ __align__(16) uint32_t g_Wdf[(size_t)64*256*128];   // K=1024 (8MB)

// ---------------- math helpers ----------------
__device__ __forceinline__ float sigf(float x){
    return __fdividef(1.f, 1.f + __expf(-x));
}
__device__ __forceinline__ float tanhf_fast(float x){
    float ax = fabsf(x);
    float t  = __expf(-2.f*ax);
    float r  = __fdividef(1.f - t, 1.f + t);
    return copysignf(r, x);
}
// float(bf16(v)) round-trip (rn)
__device__ __forceinline__ float bf16rt(float v){
    return __bfloat162float(__float2bfloat16(v));
}
// pack two floats into bf16x2: low half = flo, high half = fhi
__device__ __forceinline__ uint32_t packbf2(float flo, float fhi){
    uint32_t r; asm("cvt.rn.bf16x2.f32 %0, %1, %2;" : "=r"(r) : "f"(fhi), "f"(flo));
    return r;
}
__device__ __forceinline__ void mma_bf16(float* c, const uint32_t* a, uint32_t b0, uint32_t b1){
    asm volatile(
        "mma.sync.aligned.m16n8k16.row.col.f32.bf16.bf16.f32 "
        "{%0,%1,%2,%3}, {%4,%5,%6,%7}, {%8,%9}, {%0,%1,%2,%3};"
        : "+f"(c[0]), "+f"(c[1]), "+f"(c[2]), "+f"(c[3])
        : "r"(a[0]), "r"(a[1]), "r"(a[2]), "r"(a[3]), "r"(b0), "r"(b1));
}

// ---------------- K0a: build xcat = concat(inputs, score) ----------------
__global__ void k_build(const float* __restrict__ inp, const float* __restrict__ score){
    int i  = blockIdx.x*256 + threadIdx.x;
    int u  = i & (Uu-1);
    int bt = i >> 9;
    g_xcat[i] = (u < Ff) ? inp[bt*Ff + u] : score[bt >> 8];
}

// ---------------- K0b: dec_in0 = mean_t(x); zero enc state ----------------
__global__ void k_init(){
    int i = blockIdx.x*256 + threadIdx.x;        // < B*U
    int u = i & (Uu-1);
    int b = i >> 9;
    const float* p = &g_xcat[(b*Tt)*Uu + u];
    float s = 0.f;
    for (int t = 0; t < Tt; t++) s += p[t*Uu];
    g_xh[0][b*2*Uu + u] = s * (1.f/Tt);
    g_h[0][i] = 0.f;
    g_c[0][i] = 0.f;
}

// ---------------- weight rearrange: bf16 hi/lo fragments (m16n8k16), interleaved cols ----------------
// fragment (kb16, nb, lane): n = nb*8 + lane/4 (permuted), k = kb*16 + (lane%4)*2 (+1, +8, +9)
__global__ void k_rearr(const float* __restrict__ W, int dst_sel, int kb_off, int Krows){
    uint32_t* Wf = (dst_sel == 0) ? g_Wxf : (dst_sel == 1) ? g_Whf : g_Wdf;
    int idx = blockIdx.x*256 + threadIdx.x;      // (kb*256 + nb)*32 + lane
    int lane = idx & 31;
    int nb   = (idx >> 5) & 255;
    int kb   = idx >> 13;
    if (kb >= Krows/16) return;
    int np = nb*8 + (lane >> 2);        // permuted col
    int c  = (np & 3)*Uu + (np >> 2);   // original col = gate*512 + u
    int k0 = kb*16 + (lane & 3)*2;
    float v00 = W[(k0    )*G4 + c], v01 = W[(k0 + 1)*G4 + c];
    float v10 = W[(k0 + 8)*G4 + c], v11 = W[(k0 + 9)*G4 + c];
    float h00 = bf16rt(v00), h01 = bf16rt(v01);
    float h10 = bf16rt(v10), h11 = bf16rt(v11);
    uint4 v;
    v.x = packbf2(v00, v01);                 // b0 hi
    v.y = packbf2(v10, v11);                 // b1 hi
    v.z = packbf2(v00 - h00, v01 - h01);     // b0 lo
    v.w = packbf2(v10 - h10, v11 - h11);     // b1 lo
    *(uint4*)&Wf[(((size_t)(kb + kb_off)*256 + nb)*32 + lane)*4] = v;
}

// ---------------- bf16x3 MMA mainloop: acc = A[32-row tile] @ B[128-col tile], K-chunk 32 ----------------
// pool: As = pool[0..2047] ([buf][kk*2+mb][lane][8]), Bs = pool[2048..10239] ([buf][kk][2048])
__device__ __forceinline__ void mma_main(const float* __restrict__ A, int lda,
                                         const uint32_t* __restrict__ Bf, int K,
                                         uint32_t* pool, float (&acc)[4][4]){
    uint32_t* As = pool;          // per buf: 2kk * 2mb * 32 lanes * 8 = 1024
    uint32_t* Bs = pool + 2048;   // per buf: 2kk * 2048 = 4096

    const int t    = threadIdx.x;
    const int lane = t & 31;
    const int wid  = t >> 5;
    const int warpM = wid & 1;
    const int warpN = wid >> 1;

    const int row0 = blockIdx.y << 5;
    const int col0 = blockIdx.x << 7;
    const int NK   = K >> 5;             // 32-k chunks

    // A staging: thread reads row ar, float4 at cols ac..ac+3 of the chunk
    const int ar = t >> 3;               // 0..31
    const int ac = (t & 7) << 2;         // 0,4,..,28
    const float* Aptr = &A[(size_t)(row0 + ar)*lda + ac];
    const int r = ar & 15, mb = ar >> 4;
    int s_idx[2];
    #pragma unroll
    for (int j = 0; j < 2; j++){
        int p  = (ac >> 1) + j;          // k-pair index 0..15
        int kk = p >> 3;                 // which k16
        int kl = p & 7;                  // pair within k16
        int reg    = ((r >> 3) & 1) + ((kl >> 2) << 1);
        int lane_s = (r & 7)*4 + (kl & 3);
        s_idx[j] = ((kk*2 + mb)*32 + lane_s)*8 + reg;
    }
    const uint32_t* Bbase = Bf + (size_t)(col0 >> 3)*128;

    #pragma unroll
    for (int i = 0; i < 4; i++)
        #pragma unroll
        for (int j = 0; j < 4; j++) acc[i][j] = 0.f;

    // ---- stage chunk 0 ----
    float4 Av = *(const float4*)Aptr;
    uint4  Bv[4];
    #pragma unroll
    for (int kb = 0; kb < 2; kb++){
        const uint32_t* src = Bbase + (size_t)kb*32768;
        Bv[kb*2  ] = *(const uint4*)(src + t*4);
        Bv[kb*2+1] = *(const uint4*)(src + 1024 + t*4);
    }
    {
        float av[4] = {Av.x, Av.y, Av.z, Av.w};
        #pragma unroll
        for (int j = 0; j < 2; j++){
            float e0 = av[2*j], e1 = av[2*j+1];
            float h0 = bf16rt(e0), h1 = bf16rt(e1);
            As[s_idx[j]    ] = packbf2(e0, e1);
            As[s_idx[j] + 4] = packbf2(e0 - h0, e1 - h1);
        }
        #pragma unroll
        for (int kb = 0; kb < 2; kb++){
            *(uint4*)(Bs + kb*2048 + t*4)        = Bv[kb*2];
            *(uint4*)(Bs + kb*2048 + 1024 + t*4) = Bv[kb*2+1];
        }
    }
    __syncthreads();

    int cur = 0;
    for (int kc = 0; kc < NK; kc++){
        // prefetch next chunk (gmem -> regs)
        if (kc + 1 < NK){
            Av = *(const float4*)(Aptr + (kc+1)*32);
            #pragma unroll
            for (int kb = 0; kb < 2; kb++){
                const uint32_t* src = Bbase + (size_t)((kc+1)*2 + kb)*32768;
                Bv[kb*2  ] = *(const uint4*)(src + t*4);
                Bv[kb*2+1] = *(const uint4*)(src + 1024 + t*4);
            }
        }
        // compute from smem[cur]: 2 k16 blocks, 4 n8 tiles/warp, 3 bf16 MMAs each
        #pragma unroll
        for (int kk = 0; kk < 2; kk++){
            uint32_t ah[4], al[4];
            const uint32_t* ab = As + cur*1024 + ((kk*2 + warpM)*32 + lane)*8;
            *(uint4*)ah = *(const uint4*)(ab);
            *(uint4*)al = *(const uint4*)(ab + 4);
            #pragma unroll
            for (int nbl = 0; nbl < 4; nbl++){
                uint4 bv = *(const uint4*)(Bs + cur*4096 + kk*2048 + ((warpN*4 + nbl)*32 + lane)*4);
                mma_bf16(acc[nbl], ah, bv.z, bv.w);   // hi * lo
                mma_bf16(acc[nbl], al, bv.x, bv.y);   // lo * hi
                mma_bf16(acc[nbl], ah, bv.x, bv.y);   // hi * hi
            }
        }
        // store next chunk (regs -> smem[cur^1])
        if (kc + 1 < NK){
            float av[4] = {Av.x, Av.y, Av.z, Av.w};
            int ab2 = (cur^1)*1024;
            #pragma unroll
            for (int j = 0; j < 2; j++){
                float e0 = av[2*j], e1 = av[2*j+1];
                float h0 = bf16rt(e0), h1 = bf16rt(e1);
                As[ab2 + s_idx[j]    ] = packbf2(e0, e1);
                As[ab2 + s_idx[j] + 4] = packbf2(e0 - h0, e1 - h1);
            }
            uint32_t* bl = Bs + (cur^1)*4096;
            #pragma unroll
            for (int kb = 0; kb < 2; kb++){
                *(uint4*)(bl + kb*2048 + t*4)        = Bv[kb*2];
                *(uint4*)(bl + kb*2048 + 1024 + t*4) = Bv[kb*2+1];
            }
        }
        __syncthreads();
        cur ^= 1;
    }
    // after the final __syncthreads(), pool is reusable
}

// ---------------- big input projection: plain store (interleaved cols) ----------------
__global__ void k_gemm_xx_g(){
    __shared__ __align__(16) uint32_t pool[10240];
    float acc[4][4];
    mma_main(g_xcat, Uu, g_Wxf, Uu, pool, acc);
    const int lane = threadIdx.x & 31, wid = threadIdx.x >> 5;
    const int warpM = wid & 1, warpN = wid >> 1;
    const int gg = lane >> 2, tig = lane & 3;
    const int r0 = (blockIdx.y << 5) + warpM*16 + gg;
    const int col0 = blockIdx.x << 7;
    #pragma unroll
    for (int nbl = 0; nbl < 4; nbl++){
        int col = col0 + (warpN*4 + nbl)*8 + 2*tig;
        *(float2*)&g_Xx[(size_t)r0*G4 + col]     = make_float2(acc[nbl][0], acc[nbl][1]);
        *(float2*)&g_Xx[(size_t)(r0+8)*G4 + col] = make_float2(acc[nbl][2], acc[nbl][3]);
    }
}

// ---------------- fused encoder step: GEMM + Xx + bias + gates + state ----------------
__global__ void k_enc_step(const float* __restrict__ eb, int t){
    __shared__ __align__(16) uint32_t pool[10240];
    float acc[4][4];
    const int par = t & 1;
    mma_main(g_h[par], Uu, g_Whf, Uu, pool, acc);

    float* zs = reinterpret_cast<float*>(pool);     // [32][132] z tile (reuses pool)
    const int lane = threadIdx.x & 31, wid = threadIdx.x >> 5;
    const int warpM = wid & 1, warpN = wid >> 1;
    const int gg = lane >> 2, tig = lane & 3;
    const int rl = warpM*16 + gg;
    #pragma unroll
    for (int nbl = 0; nbl < 4; nbl++){
        int c = (warpN*4 + nbl)*8 + 2*tig;
        zs[rl*132 + c]     = acc[nbl][0]; zs[rl*132 + c + 1]     = acc[nbl][1];
        zs[(rl+8)*132 + c] = acc[nbl][2]; zs[(rl+8)*132 + c + 1] = acc[nbl][3];
    }
    __syncthreads();

    const int th  = threadIdx.x;
    const int row = th >> 3;
    const int u4  = th & 7;
    const int b   = (blockIdx.y << 5) + row;
    const int col0 = blockIdx.x << 7;
    #pragma unroll
    for (int i = 0; i < 4; i++){
        int ul = u4*4 + i;
        int ug = (blockIdx.x << 5) + ul;
        float4 z4 = *(float4*)&zs[row*132 + ul*4];
        float4 xx = *(const float4*)&g_Xx[((size_t)b*Tt + t)*G4 + col0 + ul*4];
        float zi = z4.x + xx.x + eb[ug];
        float zf = z4.y + xx.y + eb[Uu   + ug];
        float zg = z4.z + xx.z + eb[2*Uu + ug];
        float zo = z4.w + xx.w + eb[3*Uu + ug];
        int idx = b*Uu + ug;
        float cn = sigf(zf)*g_c[par][idx] + sigf(zi)*tanhf_fast(zg);
        float hn = sigf(zo)*tanhf_fast(cn);
        g_c[par^1][idx] = cn;
        g_h[par^1][idx] = hn;
        g_ench[((size_t)b*Tt + t)*Uu + ug] = __float2half(hn);
    }
}

// ---------------- dec init: copy enc-final h,c into decoder state ----------------
__global__ void k_init_dec(){
    int i = blockIdx.x*256 + threadIdx.x;
    int u = i & (Uu-1);
    int b = i >> 9;
    g_xh[0][b*2*Uu + Uu + u] = g_h[0][i];
    g_cd[0][i] = g_c[0][i];
}

// ---------------- fused decoder step: GEMM (K=1024) + bias + gates + state ----------------
__global__ void k_dec_step(const float* __restrict__ db, int s){
    __shared__ __align__(16) uint32_t pool[10240];
    float acc[4][4];
    const int par = s & 1;
    mma_main(g_xh[par], 2*Uu, g_Wdf, 2*Uu, pool, acc);

    float* zs = reinterpret_cast<float*>(pool);
    const int lane = threadIdx.x & 31, wid = threadIdx.x >> 5;
    const int warpM = wid & 1, warpN = wid >> 1;
    const int gg = lane >> 2, tig = lane & 3;
    const int rl = warpM*16 + gg;
    #pragma unroll
    for (int nbl = 0; nbl < 4; nbl++){
        int c = (warpN*4 + nbl)*8 + 2*tig;
        zs[rl*132 + c]     = acc[nbl][0]; zs[rl*132 + c + 1]     = acc[nbl][1];
        zs[(rl+8)*132 + c] = acc[nbl][2]; zs[(rl+8)*132 + c + 1] = acc[nbl][3];
    }
    __syncthreads();

    const int th  = threadIdx.x;
    const int row = th >> 3;
    const int u4  = th & 7;
    const int b   = (blockIdx.y << 5) + row;
    #pragma unroll
    for (int i = 0; i < 4; i++){
        int ul = u4*4 + i;
        int ug = (blockIdx.x << 5) + ul;
        float4 z4 = *(float4*)&zs[row*132 + ul*4];
        float zi = z4.x + db[ug];
        float zf = z4.y + db[Uu   + ug];
        float zg = z4.z + db[2*Uu + ug];
        float zo = z4.w + db[3*Uu + ug];
        int idx = b*Uu + ug;
        float cn = sigf(zf)*g_cd[par][idx] + sigf(zi)*tanhf_fast(zg);
        float hn = sigf(zo)*tanhf_fast(cn);
        g_cd[par^1][idx] = cn;
        g_xh[par^1][b*2*Uu + Uu + ug] = hn;
    }
}

// ---------------- attention (one block per batch row; enc in fp16) ----------------
__global__ void k_attn(const float* __restrict__ pw, const float* __restrict__ pb,
                       float* __restrict__ out, int s){
    int b = blockIdx.x;
    int p = (s & 1) ^ 1;                 // buffer holding this step's h / receiving xin
    __shared__ float hs[Uu];
    __shared__ float pr[Tt];
    __shared__ float red[8];
    int tid = threadIdx.x;
    hs[tid]       = g_xh[p][b*2*Uu + Uu + tid];
    hs[tid + 256] = g_xh[p][b*2*Uu + Uu + tid + 256];
    __syncthreads();
    int w = tid >> 5, lane = tid & 31;
    const __half* encb = &g_ench[(size_t)b*Tt*Uu];
    for (int t = w; t < Tt; t += 8){
        const __half2* e2 = reinterpret_cast<const __half2*>(encb + t*Uu);
        float sum = 0.f;
        #pragma unroll
        for (int u = lane*8; u < Uu; u += 256){
            int h2 = u >> 1;
            float2 p0 = __half22float2(e2[h2  ]);
            float2 p1 = __half22float2(e2[h2+1]);
            float2 p2 = __half22float2(e2[h2+2]);
            float2 p3 = __half22float2(e2[h2+3]);
            sum += p0.x*hs[u  ] + p0.y*hs[u+1] + p1.x*hs[u+2] + p1.y*hs[u+3]
                 + p2.x*hs[u+4] + p2.y*hs[u+5] + p3.x*hs[u+6] + p3.y*hs[u+7];
        }
        #pragma unroll
        for (int off = 16; off; off >>= 1) sum += __shfl_xor_sync(0xffffffffu, sum, off);
        if (lane == 0) pr[t] = sum;
    }
    __syncthreads();
    float wv = *pw, bv = *pb;
    float logit = pr[tid]*wv + bv;
    float m = logit;
    #pragma unroll
    for (int off = 16; off; off >>= 1) m = fmaxf(m, __shfl_xor_sync(0xffffffffu, m, off));
    if (lane == 0) red[w] = m;
    __syncthreads();
    m = red[0];
    #pragma unroll
    for (int i = 1; i < 8; i++) m = fmaxf(m, red[i]);
    float e  = __expf(logit - m);
    float sm = e;
    #pragma unroll
    for (int off = 16; off; off >>= 1) sm += __shfl_xor_sync(0xffffffffu, sm, off);
    __syncthreads();
    if (lane == 0) red[w] = sm;
    __syncthreads();
    sm = 0.f;
    #pragma unroll
    for (int i = 0; i < 8; i++) sm += red[i];
    float pv = e * __fdividef(1.f, sm);
    pr[tid] = pv;
    out[((size_t)b*Tt + s)*Tt + tid] = pv;
    __syncthreads();
    const __half2* ep = reinterpret_cast<const __half2*>(encb);
    float x0 = 0.f, x1 = 0.f;
    for (int t = 0; t < Tt; t++){
        float pt = pr[t];
        float2 ev = __half22float2(ep[t*(Uu/2) + tid]);
        x0 += pt*ev.x; x1 += pt*ev.y;
    }
    g_xh[p][b*2*Uu + tid*2    ] = x0;
    g_xh[p][b*2*Uu + tid*2 + 1] = x1;
}

// ---------------- launch ----------------
extern "C" void kernel_launch(void* const* d_in, const int* in_sizes, int n_in,
                              void* d_out, int out_size){
    const float* inputs = (const float*)d_in[0];
    const float* score  = (const float*)d_in[1];
    const float* eWx    = (const float*)d_in[2];
    const float* eWh    = (const float*)d_in[3];
    const float* eb     = (const float*)d_in[4];
    const float* dWx    = (const float*)d_in[5];
    const float* dWh    = (const float*)d_in[6];
    const float* db     = (const float*)d_in[7];
    const float* pw     = (const float*)d_in[8];
    const float* pb     = (const float*)d_in[9];
    float* out = (float*)d_out;

    k_build<<<Bb*Tt*Uu/256, 256>>>(inputs, score);
    k_init<<<Bb*Uu/256, 256>>>();

    // weight rearrange (bf16 hi/lo fragments, unit-interleaved columns)
    k_rearr<<<1024, 256>>>(eWx, 0, 0,  512);
    k_rearr<<<1024, 256>>>(eWh, 1, 0,  512);
    k_rearr<<<1024, 256>>>(dWx, 2, 0,  512);
    k_rearr<<<1024, 256>>>(dWh, 2, 32, 512);

    // big input projection: [65536 x 512] @ [512 x 2048]
    k_gemm_xx_g<<<dim3(16, 2048), 256>>>();

    // encoder recurrence (1 fused kernel per step)
    for (int t = 0; t < Tt; t++)
        k_enc_step<<<dim3(16, 8), 256>>>(eb, t);

    k_init_dec<<<Bb*Uu/256, 256>>>();

    // decoder recurrence + attention (2 kernels per step)
    for (int s = 0; s < Tt; s++){
        k_dec_step<<<dim3(16, 8), 256>>>(db, s);
        k_attn<<<Bb, 256>>>(pw, pb, out, s);
    }
}

// round 13
// speedup vs baseline: 3.6439x; 1.0948x over previous
#include <cuda_runtime.h>
#include <cuda_fp16.h>
#include <cuda_bf16.h>
#include <cstdint>

#define Bb 256
#define Tt 256
#define Ff 511
#define Uu 512
#define G4 2048   // 4*U

// ---------------- scratch (static device globals; no allocation) ----------------
__device__ float g_xcat[Bb*Tt*Uu];                     // [B*T, U] concat(inputs, score)
__device__ float g_Xx  [Bb*Tt*G4];                     // [B*T, 4U] x @ enc_Wx (unit-interleaved cols)
__device__ __half g_ench[(size_t)Bb*Tt*Uu];            // [B, T, U] encoder outputs (fp16)
__device__ float g_h [2][Bb*Uu];                       // encoder hidden ping-pong
__device__ float g_cfin[Bb*Uu];                        // encoder final cell (enc->dec handoff)
__device__ float g_xh[2][Bb*2*Uu];                     // decoder [xin | h] concat ping-pong
// bf16-split fragment weights: [kb16][nb][lane][4 uints] = {b0_hi, b1_hi, b0_lo, b1_lo}
__device__ __align__(16) uint32_t g_Wxf[(size_t)32*256*128];   // K=512  (4MB)
__device__ __align__(16) uint32_t g_Whf[(size_t)32*256*128];   // K=512  (4MB)
__device__ __align__(16) uint32_t g_Wdf[(size_t)64*256*128];   // K=1024 (8MB)
// software grid-barrier counters (monotonic per launch; zeroed in k_init)
__device__ unsigned g_bar_e;
__device__ unsigned g_bar_d;

// ---------------- math helpers ----------------
__device__ __forceinline__ float sigf(float x){
    return __fdividef(1.f, 1.f + __expf(-x));
}
__device__ __forceinline__ float tanhf_fast(float x){
    float ax = fabsf(x);
    float t  = __expf(-2.f*ax);
    float r  = __fdividef(1.f - t, 1.f + t);
    return copysignf(r, x);
}
__device__ __forceinline__ float bf16rt(float v){
    return __bfloat162float(__float2bfloat16(v));
}
__device__ __forceinline__ uint32_t packbf2(float flo, float fhi){
    uint32_t r; asm("cvt.rn.bf16x2.f32 %0, %1, %2;" : "=r"(r) : "f"(fhi), "f"(flo));
    return r;
}
__device__ __forceinline__ void mma_bf16(float* c, const uint32_t* a, uint32_t b0, uint32_t b1){
    asm volatile(
        "mma.sync.aligned.m16n8k16.row.col.f32.bf16.bf16.f32 "
        "{%0,%1,%2,%3}, {%4,%5,%6,%7}, {%8,%9}, {%0,%1,%2,%3};"
        : "+f"(c[0]), "+f"(c[1]), "+f"(c[2]), "+f"(c[3])
        : "r"(a[0]), "r"(a[1]), "r"(a[2]), "r"(a[3]), "r"(b0), "r"(b1));
}

// ---------------- software grid barrier (release/acquire via fence + atomic) ----------------
__device__ __forceinline__ void grid_bar(unsigned* ctr, unsigned target){
    __syncthreads();                       // all CTA writes ordered before thread0's fence
    if (threadIdx.x == 0){
        __threadfence();                   // release
        atomicAdd(ctr, 1u);
        while (*(volatile unsigned*)ctr < target) __nanosleep(40);
        __threadfence();                   // acquire
    }
    __syncthreads();                       // publish to whole CTA
}

// ---------------- K0a: build xcat = concat(inputs, score) ----------------
__global__ void k_build(const float* __restrict__ inp, const float* __restrict__ score){
    int i  = blockIdx.x*256 + threadIdx.x;
    int u  = i & (Uu-1);
    int bt = i >> 9;
    g_xcat[i] = (u < Ff) ? inp[bt*Ff + u] : score[bt >> 8];
}

// ---------------- K0b: dec_in0 = mean_t(x); zero enc h0; reset barriers ----------------
__global__ void k_init(){
    int i = blockIdx.x*256 + threadIdx.x;        // < B*U
    if (i == 0){ g_bar_e = 0; g_bar_d = 0; }
    int u = i & (Uu-1);
    int b = i >> 9;
    const float* p = &g_xcat[(b*Tt)*Uu + u];
    float s = 0.f;
    for (int t = 0; t < Tt; t++) s += p[t*Uu];
    g_xh[0][b*2*Uu + u] = s * (1.f/Tt);
    g_h[0][i] = 0.f;
}

// ---------------- weight rearrange: bf16 hi/lo fragments (m16n8k16), interleaved cols ----------------
__global__ void k_rearr(const float* __restrict__ W, int dst_sel, int kb_off, int Krows){
    uint32_t* Wf = (dst_sel == 0) ? g_Wxf : (dst_sel == 1) ? g_Whf : g_Wdf;
    int idx = blockIdx.x*256 + threadIdx.x;      // (kb*256 + nb)*32 + lane
    int lane = idx & 31;
    int nb   = (idx >> 5) & 255;
    int kb   = idx >> 13;
    if (kb >= Krows/16) return;
    int np = nb*8 + (lane >> 2);        // permuted col
    int c  = (np & 3)*Uu + (np >> 2);   // original col = gate*512 + u
    int k0 = kb*16 + (lane & 3)*2;
    float v00 = W[(k0    )*G4 + c], v01 = W[(k0 + 1)*G4 + c];
    float v10 = W[(k0 + 8)*G4 + c], v11 = W[(k0 + 9)*G4 + c];
    float h00 = bf16rt(v00), h01 = bf16rt(v01);
    float h10 = bf16rt(v10), h11 = bf16rt(v11);
    uint4 v;
    v.x = packbf2(v00, v01);
    v.y = packbf2(v10, v11);
    v.z = packbf2(v00 - h00, v01 - h01);
    v.w = packbf2(v10 - h10, v11 - h11);
    *(uint4*)&Wf[(((size_t)(kb + kb_off)*256 + nb)*32 + lane)*4] = v;
}

// ---------------- bf16x3 MMA mainloop: acc = A[32-row tile] @ B[128-col tile], K-chunk 32 ----------------
__device__ __forceinline__ void mma_main(const float* __restrict__ A, int lda,
                                         const uint32_t* __restrict__ Bf, int K,
                                         uint32_t* pool, float (&acc)[4][4],
                                         int row0, int col0){
    uint32_t* As = pool;          // per buf: 1024
    uint32_t* Bs = pool + 2048;   // per buf: 4096

    const int t    = threadIdx.x;
    const int lane = t & 31;
    const int wid  = t >> 5;
    const int warpM = wid & 1;
    const int warpN = wid >> 1;
    const int NK   = K >> 5;

    const int ar = t >> 3;
    const int ac = (t & 7) << 2;
    const float* Aptr = &A[(size_t)(row0 + ar)*lda + ac];
    const int r = ar & 15, mb = ar >> 4;
    int s_idx[2];
    #pragma unroll
    for (int j = 0; j < 2; j++){
        int p  = (ac >> 1) + j;
        int kk = p >> 3;
        int kl = p & 7;
        int reg    = ((r >> 3) & 1) + ((kl >> 2) << 1);
        int lane_s = (r & 7)*4 + (kl & 3);
        s_idx[j] = ((kk*2 + mb)*32 + lane_s)*8 + reg;
    }
    const uint32_t* Bbase = Bf + (size_t)(col0 >> 3)*128;

    #pragma unroll
    for (int i = 0; i < 4; i++)
        #pragma unroll
        for (int j = 0; j < 4; j++) acc[i][j] = 0.f;

    // ---- stage chunk 0 ----
    float4 Av = *(const float4*)Aptr;
    uint4  Bv[4];
    #pragma unroll
    for (int kb = 0; kb < 2; kb++){
        const uint32_t* src = Bbase + (size_t)kb*32768;
        Bv[kb*2  ] = *(const uint4*)(src + t*4);
        Bv[kb*2+1] = *(const uint4*)(src + 1024 + t*4);
    }
    {
        float av[4] = {Av.x, Av.y, Av.z, Av.w};
        #pragma unroll
        for (int j = 0; j < 2; j++){
            float e0 = av[2*j], e1 = av[2*j+1];
            float h0 = bf16rt(e0), h1 = bf16rt(e1);
            As[s_idx[j]    ] = packbf2(e0, e1);
            As[s_idx[j] + 4] = packbf2(e0 - h0, e1 - h1);
        }
        #pragma unroll
        for (int kb = 0; kb < 2; kb++){
            *(uint4*)(Bs + kb*2048 + t*4)        = Bv[kb*2];
            *(uint4*)(Bs + kb*2048 + 1024 + t*4) = Bv[kb*2+1];
        }
    }
    __syncthreads();

    int cur = 0;
    for (int kc = 0; kc < NK; kc++){
        if (kc + 1 < NK){
            Av = *(const float4*)(Aptr + (kc+1)*32);
            #pragma unroll
            for (int kb = 0; kb < 2; kb++){
                const uint32_t* src = Bbase + (size_t)((kc+1)*2 + kb)*32768;
                Bv[kb*2  ] = *(const uint4*)(src + t*4);
                Bv[kb*2+1] = *(const uint4*)(src + 1024 + t*4);
            }
        }
        #pragma unroll
        for (int kk = 0; kk < 2; kk++){
            uint32_t ah[4], al[4];
            const uint32_t* ab = As + cur*1024 + ((kk*2 + warpM)*32 + lane)*8;
            *(uint4*)ah = *(const uint4*)(ab);
            *(uint4*)al = *(const uint4*)(ab + 4);
            #pragma unroll
            for (int nbl = 0; nbl < 4; nbl++){
                uint4 bv = *(const uint4*)(Bs + cur*4096 + kk*2048 + ((warpN*4 + nbl)*32 + lane)*4);
                mma_bf16(acc[nbl], ah, bv.z, bv.w);   // hi * lo
                mma_bf16(acc[nbl], al, bv.x, bv.y);   // lo * hi
                mma_bf16(acc[nbl], ah, bv.x, bv.y);   // hi * hi
            }
        }
        if (kc + 1 < NK){
            float av[4] = {Av.x, Av.y, Av.z, Av.w};
            int ab2 = (cur^1)*1024;
            #pragma unroll
            for (int j = 0; j < 2; j++){
                float e0 = av[2*j], e1 = av[2*j+1];
                float h0 = bf16rt(e0), h1 = bf16rt(e1);
                As[ab2 + s_idx[j]    ] = packbf2(e0, e1);
                As[ab2 + s_idx[j] + 4] = packbf2(e0 - h0, e1 - h1);
            }
            uint32_t* bl = Bs + (cur^1)*4096;
            #pragma unroll
            for (int kb = 0; kb < 2; kb++){
                *(uint4*)(bl + kb*2048 + t*4)        = Bv[kb*2];
                *(uint4*)(bl + kb*2048 + 1024 + t*4) = Bv[kb*2+1];
            }
        }
        __syncthreads();
        cur ^= 1;
    }
}

// ---------------- big input projection: plain store (interleaved cols) ----------------
__global__ void k_gemm_xx_g(){
    __shared__ __align__(16) uint32_t pool[10240];
    float acc[4][4];
    mma_main(g_xcat, Uu, g_Wxf, Uu, pool, acc, blockIdx.y << 5, blockIdx.x << 7);
    const int lane = threadIdx.x & 31, wid = threadIdx.x >> 5;
    const int warpM = wid & 1, warpN = wid >> 1;
    const int gg = lane >> 2, tig = lane & 3;
    const int r0 = (blockIdx.y << 5) + warpM*16 + gg;
    const int col0 = blockIdx.x << 7;
    #pragma unroll
    for (int nbl = 0; nbl < 4; nbl++){
        int col = col0 + (warpN*4 + nbl)*8 + 2*tig;
        *(float2*)&g_Xx[(size_t)r0*G4 + col]     = make_float2(acc[nbl][0], acc[nbl][1]);
        *(float2*)&g_Xx[(size_t)(r0+8)*G4 + col] = make_float2(acc[nbl][2], acc[nbl][3]);
    }
}

// ---------------- persistent encoder: 256 steps, 1 grid barrier/step, c in regs ----------------
__global__ __launch_bounds__(256, 1) void k_enc_all(const float* __restrict__ eb){
    __shared__ __align__(16) uint32_t pool[10240];
    const int cta = blockIdx.x;              // 0..127
    const int ctx = cta & 15, cty = cta >> 4;
    const int row0 = cty << 5, col0 = ctx << 7;
    const int th = threadIdx.x;
    const int lane = th & 31, wid = th >> 5;
    const int warpM = wid & 1, warpN = wid >> 1;
    const int gg = lane >> 2, tig = lane & 3;
    const int rl = warpM*16 + gg;
    const int erow = th >> 3, u4 = th & 7;
    const int b = row0 + erow;

    float creg[4] = {0.f, 0.f, 0.f, 0.f};
    unsigned tgt = 0;

    for (int t = 0; t < Tt; t++){
        const int par = t & 1;
        float acc[4][4];
        mma_main(g_h[par], Uu, g_Whf, Uu, pool, acc, row0, col0);

        float* zs = reinterpret_cast<float*>(pool);   // [32][132]
        #pragma unroll
        for (int nbl = 0; nbl < 4; nbl++){
            int c = (warpN*4 + nbl)*8 + 2*tig;
            zs[rl*132 + c]     = acc[nbl][0]; zs[rl*132 + c + 1]     = acc[nbl][1];
            zs[(rl+8)*132 + c] = acc[nbl][2]; zs[(rl+8)*132 + c + 1] = acc[nbl][3];
        }
        __syncthreads();

        const float* xxrow = &g_Xx[((size_t)b*Tt + t)*G4 + col0];
        #pragma unroll
        for (int i = 0; i < 4; i++){
            int ul = u4*4 + i;
            int ug = (ctx << 5) + ul;
            float4 z4 = *(float4*)&zs[erow*132 + ul*4];
            float4 xx = *(const float4*)&xxrow[ul*4];
            float zi = z4.x + xx.x + eb[ug];
            float zf = z4.y + xx.y + eb[Uu   + ug];
            float zg = z4.z + xx.z + eb[2*Uu + ug];
            float zo = z4.w + xx.w + eb[3*Uu + ug];
            float cn = sigf(zf)*creg[i] + sigf(zi)*tanhf_fast(zg);
            float hn = sigf(zo)*tanhf_fast(cn);
            creg[i] = cn;
            g_h[par^1][b*Uu + ug] = hn;
            g_ench[((size_t)b*Tt + t)*Uu + ug] = __float2half(hn);
        }
        tgt += 128;
        grid_bar(&g_bar_e, tgt);
    }
    // hand off final cell state (h final is already in g_h[0])
    #pragma unroll
    for (int i = 0; i < 4; i++)
        g_cfin[b*Uu + (ctx << 5) + u4*4 + i] = creg[i];
}

// ---------------- dec init: copy enc-final h into decoder concat ----------------
__global__ void k_init_dec(){
    int i = blockIdx.x*256 + threadIdx.x;
    int u = i & (Uu-1);
    int b = i >> 9;
    g_xh[0][b*2*Uu + Uu + u] = g_h[0][i];
}

// ---------------- attention body (per-CTA, one batch row) ----------------
__device__ __forceinline__ void attn_body(uint32_t* pool, int b, int p, int s,
                                          float wv, float bv, float* __restrict__ out){
    float* hs  = reinterpret_cast<float*>(pool);          // 512
    float* pr  = hs + Uu;                                 // 256
    float* red = pr + Tt;                                 // 8
    int tid = threadIdx.x;
    hs[tid]       = g_xh[p][b*2*Uu + Uu + tid];
    hs[tid + 256] = g_xh[p][b*2*Uu + Uu + tid + 256];
    __syncthreads();
    int w = tid >> 5, lane = tid & 31;
    const __half* encb = &g_ench[(size_t)b*Tt*Uu];
    for (int t = w; t < Tt; t += 8){
        const __half2* e2 = reinterpret_cast<const __half2*>(encb + t*Uu);
        float sum = 0.f;
        #pragma unroll
        for (int u = lane*8; u < Uu; u += 256){
            int h2 = u >> 1;
            float2 p0 = __half22float2(e2[h2  ]);
            float2 p1 = __half22float2(e2[h2+1]);
            float2 p2 = __half22float2(e2[h2+2]);
            float2 p3 = __half22float2(e2[h2+3]);
            sum += p0.x*hs[u  ] + p0.y*hs[u+1] + p1.x*hs[u+2] + p1.y*hs[u+3]
                 + p2.x*hs[u+4] + p2.y*hs[u+5] + p3.x*hs[u+6] + p3.y*hs[u+7];
        }
        #pragma unroll
        for (int off = 16; off; off >>= 1) sum += __shfl_xor_sync(0xffffffffu, sum, off);
        if (lane == 0) pr[t] = sum;
    }
    __syncthreads();
    float logit = pr[tid]*wv + bv;
    float m = logit;
    #pragma unroll
    for (int off = 16; off; off >>= 1) m = fmaxf(m, __shfl_xor_sync(0xffffffffu, m, off));
    if (lane == 0) red[w] = m;
    __syncthreads();
    m = red[0];
    #pragma unroll
    for (int i = 1; i < 8; i++) m = fmaxf(m, red[i]);
    float e  = __expf(logit - m);
    float sm = e;
    #pragma unroll
    for (int off = 16; off; off >>= 1) sm += __shfl_xor_sync(0xffffffffu, sm, off);
    __syncthreads();
    if (lane == 0) red[w] = sm;
    __syncthreads();
    sm = 0.f;
    #pragma unroll
    for (int i = 0; i < 8; i++) sm += red[i];
    float pv = e * __fdividef(1.f, sm);
    pr[tid] = pv;
    out[((size_t)b*Tt + s)*Tt + tid] = pv;
    __syncthreads();
    const __half2* ep = reinterpret_cast<const __half2*>(encb);
    float x0 = 0.f, x1 = 0.f;
    for (int t = 0; t < Tt; t++){
        float pt = pr[t];
        float2 ev = __half22float2(ep[t*(Uu/2) + tid]);
        x0 += pt*ev.x; x1 += pt*ev.y;
    }
    g_xh[p][b*2*Uu + tid*2    ] = x0;
    g_xh[p][b*2*Uu + tid*2 + 1] = x1;
}

// ---------------- persistent decoder: 256 steps, GEMM on CTAs<128, attn on all 256 ----------------
__global__ __launch_bounds__(256, 2) void k_dec_all(const float* __restrict__ db,
                                                    const float* __restrict__ pw,
                                                    const float* __restrict__ pb,
                                                    float* __restrict__ out){
    __shared__ __align__(16) uint32_t pool[10240];
    const int cta = blockIdx.x;              // 0..255
    const bool gem = (cta < 128);
    const int ctx = cta & 15, cty = (cta >> 4) & 7;
    const int row0 = cty << 5, col0 = ctx << 7;
    const int th = threadIdx.x;
    const int lane = th & 31, wid = th >> 5;
    const int warpM = wid & 1, warpN = wid >> 1;
    const int gg = lane >> 2, tig = lane & 3;
    const int rl = warpM*16 + gg;
    const int erow = th >> 3, u4 = th & 7;
    const int b = row0 + erow;

    const float wv = *pw, bv = *pb;

    float creg[4];
    if (gem){
        #pragma unroll
        for (int i = 0; i < 4; i++)
            creg[i] = g_cfin[b*Uu + (ctx << 5) + u4*4 + i];
    }

    unsigned tgt = 0;
    for (int s = 0; s < Tt; s++){
        const int par = s & 1;
        if (gem){
            float acc[4][4];
            mma_main(g_xh[par], 2*Uu, g_Wdf, 2*Uu, pool, acc, row0, col0);

            float* zs = reinterpret_cast<float*>(pool);
            #pragma unroll
            for (int nbl = 0; nbl < 4; nbl++){
                int c = (warpN*4 + nbl)*8 + 2*tig;
                zs[rl*132 + c]     = acc[nbl][0]; zs[rl*132 + c + 1]     = acc[nbl][1];
                zs[(rl+8)*132 + c] = acc[nbl][2]; zs[(rl+8)*132 + c + 1] = acc[nbl][3];
            }
            __syncthreads();
            #pragma unroll
            for (int i = 0; i < 4; i++){
                int ul = u4*4 + i;
                int ug = (ctx << 5) + ul;
                float4 z4 = *(float4*)&zs[erow*132 + ul*4];
                float zi = z4.x + db[ug];
                float zf = z4.y + db[Uu   + ug];
                float zg = z4.z + db[2*Uu + ug];
                float zo = z4.w + db[3*Uu + ug];
                float cn = sigf(zf)*creg[i] + sigf(zi)*tanhf_fast(zg);
                float hn = sigf(zo)*tanhf_fast(cn);
                creg[i] = cn;
                g_xh[par^1][b*2*Uu + Uu + ug] = hn;
            }
        }
        tgt += 256;
        grid_bar(&g_bar_d, tgt);            // h(s) visible to all

        attn_body(pool, cta, par^1, s, wv, bv, out);

        tgt += 256;
        grid_bar(&g_bar_d, tgt);            // xin(s) visible before next GEMM
    }
}

// ---------------- launch ----------------
extern "C" void kernel_launch(void* const* d_in, const int* in_sizes, int n_in,
                              void* d_out, int out_size){
    const float* inputs = (const float*)d_in[0];
    const float* score  = (const float*)d_in[1];
    const float* eWx    = (const float*)d_in[2];
    const float* eWh    = (const float*)d_in[3];
    const float* eb     = (const float*)d_in[4];
    const float* dWx    = (const float*)d_in[5];
    const float* dWh    = (const float*)d_in[6];
    const float* db     = (const float*)d_in[7];
    const float* pw     = (const float*)d_in[8];
    const float* pb     = (const float*)d_in[9];
    float* out = (float*)d_out;

    k_build<<<Bb*Tt*Uu/256, 256>>>(inputs, score);
    k_init<<<Bb*Uu/256, 256>>>();

    // weight rearrange (bf16 hi/lo fragments, unit-interleaved columns)
    k_rearr<<<1024, 256>>>(eWx, 0, 0,  512);
    k_rearr<<<1024, 256>>>(eWh, 1, 0,  512);
    k_rearr<<<1024, 256>>>(dWx, 2, 0,  512);
    k_rearr<<<1024, 256>>>(dWh, 2, 32, 512);

    // big input projection: [65536 x 512] @ [512 x 2048]
    k_gemm_xx_g<<<dim3(16, 2048), 256>>>();

    // persistent encoder (128 CTAs, all resident at occ>=1)
    k_enc_all<<<128, 256>>>(eb);

    k_init_dec<<<Bb*Uu/256, 256>>>();

    // persistent decoder (256 CTAs, all resident at occ 2)
    k_dec_all<<<256, 256>>>(db, pw, pb, out);
}